// round 13
// baseline (speedup 1.0000x reference)
#include <cuda_runtime.h>
#include <float.h>
#include <stdint.h>

#define BN 4096
#define KN 32768
#define DN 128
#define HN 3
#define NTILE 128
#define NTILES (KN / NTILE)            // 256
#define NSPLIT 8
#define TILES_PER_CTA (KN / NSPLIT / NTILE)  // 32
#define TPB 256
#define EPS 1e-3f

// ---------------- scratch (static; no allocations) ----------------
__device__ float g_resid[BN * DN];
__device__ float g_quant[BN * DN];
__device__ float g_rnorm[BN];
__device__ float g_wnorm[HN * KN];
__device__ uint4 g_embq[(size_t)HN * KN * 8];   // int8 codes, 8 uint4 per row
__device__ uint4 g_residq[BN * 8];
__device__ float g_sw[HN * KN];                  // per-code int8 scale
__device__ float g_l1w[HN * KN];                 // per-code true L1 norm
__device__ float g_sr[BN];                       // per-row int8 scale
__device__ float g_l1qr[BN];                     // sr * sum|r_hat|
__device__ float g_tmaxsw[HN * NTILES];
__device__ float g_tmaxl1w[HN * NTILES];
__device__ float g_lb[(size_t)BN * NTILES];
__device__ float g_ub[(size_t)BN * NTILES];
__device__ int   g_codes[BN * HN];

// ---------------------------------------------------------------------------
// XLA-style exact row sum(x*x): separate mul/add roundings + shfl tree.
__device__ __forceinline__ float row_sumsq_xla(const float* __restrict__ x, int lane) {
    float acc = 0.0f;
    #pragma unroll
    for (int i = 0; i < 4; i++) {
        float v = x[lane + 32 * i];
        acc = __fadd_rn(acc, __fmul_rn(v, v));
    }
    #pragma unroll
    for (int o = 16; o; o >>= 1)
        acc = __fadd_rn(acc, __shfl_down_sync(0xffffffffu, acc, o));
    return acc;
}

__global__ void prep_kernel(const float* __restrict__ in) {
    int i = blockIdx.x * blockDim.x + threadIdx.x;
    if (i < BN * DN) { g_resid[i] = in[i]; g_quant[i] = 0.0f; }
}

__global__ void wnorm_kernel(const float* __restrict__ emb) {
    int row  = blockIdx.x * 8 + (threadIdx.x >> 5);
    int lane = threadIdx.x & 31;
    if (row >= HN * KN) return;
    float s = row_sumsq_xla(emb + (size_t)row * DN, lane);
    if (lane == 0) g_wnorm[row] = s;
}

__global__ void rnorm_kernel() {
    int row  = blockIdx.x * 8 + (threadIdx.x >> 5);
    int lane = threadIdx.x & 31;
    if (row >= BN) return;
    float s = row_sumsq_xla(g_resid + (size_t)row * DN, lane);
    if (lane == 0) g_rnorm[row] = s;
}

// ---------------------------------------------------------------------------
// int8 quantization. One warp per row; lane handles elems 4*lane..4*lane+3
// (matches the packed-int k-order needed by dp4a).
__device__ __forceinline__ int clamp127(int v) { return v < -127 ? -127 : (v > 127 ? 127 : v); }

__global__ void embq_kernel(const float* __restrict__ emb) {
    int row  = blockIdx.x * 8 + (threadIdx.x >> 5);
    int lane = threadIdx.x & 31;
    if (row >= HN * KN) return;
    float4 v = ((const float4*)(emb + (size_t)row * DN))[lane];
    float am = fmaxf(fmaxf(fabsf(v.x), fabsf(v.y)), fmaxf(fabsf(v.z), fabsf(v.w)));
    float l1 = fabsf(v.x) + fabsf(v.y) + fabsf(v.z) + fabsf(v.w);
    #pragma unroll
    for (int o = 16; o; o >>= 1) {
        am = fmaxf(am, __shfl_xor_sync(0xffffffffu, am, o));
        l1 = l1 + __shfl_xor_sync(0xffffffffu, l1, o);
    }
    float sw  = am * (1.0f / 127.0f);
    float inv = am > 0.0f ? 127.0f / am : 0.0f;
    int q0 = clamp127(__float2int_rn(v.x * inv));
    int q1 = clamp127(__float2int_rn(v.y * inv));
    int q2 = clamp127(__float2int_rn(v.z * inv));
    int q3 = clamp127(__float2int_rn(v.w * inv));
    ((int*)g_embq)[(size_t)row * 32 + lane] =
        (q0 & 0xff) | ((q1 & 0xff) << 8) | ((q2 & 0xff) << 16) | ((q3 & 0xff) << 24);
    if (lane == 0) { g_sw[row] = sw; g_l1w[row] = l1; }
}

__global__ void residq_kernel() {
    int row  = blockIdx.x * 8 + (threadIdx.x >> 5);
    int lane = threadIdx.x & 31;
    if (row >= BN) return;
    float4 v = ((const float4*)(g_resid + (size_t)row * DN))[lane];
    float am = fmaxf(fmaxf(fabsf(v.x), fabsf(v.y)), fmaxf(fabsf(v.z), fabsf(v.w)));
    #pragma unroll
    for (int o = 16; o; o >>= 1)
        am = fmaxf(am, __shfl_xor_sync(0xffffffffu, am, o));
    float sr  = am * (1.0f / 127.0f);
    float inv = am > 0.0f ? 127.0f / am : 0.0f;
    int q0 = clamp127(__float2int_rn(v.x * inv));
    int q1 = clamp127(__float2int_rn(v.y * inv));
    int q2 = clamp127(__float2int_rn(v.z * inv));
    int q3 = clamp127(__float2int_rn(v.w * inv));
    ((int*)g_residq)[(size_t)row * 32 + lane] =
        (q0 & 0xff) | ((q1 & 0xff) << 8) | ((q2 & 0xff) << 16) | ((q3 & 0xff) << 24);
    int asum = abs(q0) + abs(q1) + abs(q2) + abs(q3);
    #pragma unroll
    for (int o = 16; o; o >>= 1)
        asum += __shfl_xor_sync(0xffffffffu, asum, o);
    if (lane == 0) { g_sr[row] = sr; g_l1qr[row] = sr * (float)asum; }
}

// per-tile max of sw and l1w (for the coarse per-tile error bound)
__global__ void tilemax_kernel() {
    int t    = blockIdx.x * 8 + (threadIdx.x >> 5);
    int lane = threadIdx.x & 31;
    if (t >= HN * NTILES) return;
    float ms = 0.0f, ml = 0.0f;
    #pragma unroll
    for (int i = 0; i < 4; i++) {
        int idx = t * NTILE + lane + 32 * i;
        ms = fmaxf(ms, g_sw[idx]);
        ml = fmaxf(ml, g_l1w[idx]);
    }
    #pragma unroll
    for (int o = 16; o; o >>= 1) {
        ms = fmaxf(ms, __shfl_xor_sync(0xffffffffu, ms, o));
        ml = fmaxf(ml, __shfl_xor_sync(0xffffffffu, ml, o));
    }
    if (lane == 0) { g_tmaxsw[t] = ms; g_tmaxl1w[t] = ml; }
}

// ---------------------------------------------------------------------------
// dp4a screen: 128 rows x 128 codes per tile, 256 threads, 8x8 micro-tile.
// Integer dot is exact; writes sound score-interval [lb, ub] per (row, tile).
__global__ __launch_bounds__(TPB)
void screen_kernel(int h) {
    __shared__ int   As[32][132];    // [k4][row]
    __shared__ int   Bs[32][132];    // [k4][code]
    __shared__ float wns[NTILE];
    __shared__ float sws2[NTILE];    // 2 * sw

    const int tid = threadIdx.x;
    const int tx = tid & 15, ty = tid >> 4;
    const int mBase = blockIdx.x * 128;
    const int kSplitBase = blockIdx.y * (KN / NSPLIT);

    // stage A (int8 resid tile)
    #pragma unroll
    for (int it = 0; it < 4; it++) {
        int item = tid + TPB * it;           // 0..1023
        int r  = item >> 3;                  // 0..127
        int u4 = item & 7;                   // uint4 unit
        uint4 v = g_residq[(size_t)(mBase + r) * 8 + u4];
        As[u4 * 4 + 0][r] = (int)v.x;
        As[u4 * 4 + 1][r] = (int)v.y;
        As[u4 * 4 + 2][r] = (int)v.z;
        As[u4 * 4 + 3][r] = (int)v.w;
    }

    float srr[8], l1r[8];
    #pragma unroll
    for (int i = 0; i < 8; i++) {
        srr[i] = g_sr[mBase + i * 16 + ty];
        l1r[i] = g_l1qr[mBase + i * 16 + ty];
    }

    // prefetch B tile 0
    uint4 pb[4];
    #pragma unroll
    for (int it = 0; it < 4; it++) {
        int item = tid + TPB * it;
        int c  = item >> 3;
        int u4 = item & 7;
        pb[it] = g_embq[((size_t)h * KN + kSplitBase + c) * 8 + u4];
    }

    for (int t = 0; t < TILES_PER_CTA; t++) {
        const int kTile = blockIdx.y * TILES_PER_CTA + t;
        const int kBase = kSplitBase + t * NTILE;

        __syncthreads();      // previous tile's reads done (and A staged at t=0)
        #pragma unroll
        for (int it = 0; it < 4; it++) {
            int item = tid + TPB * it;
            int c  = item >> 3;
            int u4 = item & 7;
            Bs[u4 * 4 + 0][c] = (int)pb[it].x;
            Bs[u4 * 4 + 1][c] = (int)pb[it].y;
            Bs[u4 * 4 + 2][c] = (int)pb[it].z;
            Bs[u4 * 4 + 3][c] = (int)pb[it].w;
        }
        if (tid < NTILE) {
            wns[tid]  = g_wnorm[h * KN + kBase + tid];
            sws2[tid] = 2.0f * g_sw[h * KN + kBase + tid];
        }
        __syncthreads();

        if (t + 1 < TILES_PER_CTA) {
            #pragma unroll
            for (int it = 0; it < 4; it++) {
                int item = tid + TPB * it;
                int c  = item >> 3;
                int u4 = item & 7;
                pb[it] = g_embq[((size_t)h * KN + kBase + NTILE + c) * 8 + u4];
            }
        }

        int acc[8][8];
        #pragma unroll
        for (int i = 0; i < 8; i++)
            #pragma unroll
            for (int j = 0; j < 8; j++) acc[i][j] = 0;

        #pragma unroll 4
        for (int u = 0; u < 32; u++) {
            int a[8], b[8];
            #pragma unroll
            for (int i = 0; i < 8; i++) a[i] = As[u][i * 16 + ty];
            #pragma unroll
            for (int j = 0; j < 8; j++) b[j] = Bs[u][j * 16 + tx];
            #pragma unroll
            for (int i = 0; i < 8; i++)
                #pragma unroll
                for (int j = 0; j < 8; j++)
                    acc[i][j] = __dp4a(a[i], b[j], acc[i][j]);
        }

        // epilogue: per-row tile min of s_hat, then +- per-row error bound
        float msw = g_tmaxsw[h * NTILES + kTile];
        float ml1 = g_tmaxl1w[h * NTILES + kTile];
        float mn[8];
        #pragma unroll
        for (int i = 0; i < 8; i++) mn[i] = FLT_MAX;
        #pragma unroll
        for (int j = 0; j < 8; j++) {
            int cl = j * 16 + tx;
            float wnc = wns[cl], s2 = sws2[cl];
            #pragma unroll
            for (int i = 0; i < 8; i++) {
                float f  = (float)acc[i][j];
                float sh = wnc - srr[i] * (s2 * f);
                mn[i] = fminf(mn[i], sh);
            }
        }
        #pragma unroll
        for (int i = 0; i < 8; i++) {
            #pragma unroll
            for (int o = 1; o < 16; o <<= 1)
                mn[i] = fminf(mn[i], __shfl_xor_sync(0xffffffffu, mn[i], o));
            if (tx == 0) {
                float e2 = msw * l1r[i] + srr[i] * ml1 + EPS;
                size_t idx = (size_t)(mBase + i * 16 + ty) * NTILES + kTile;
                g_lb[idx] = mn[i] - e2;
                g_ub[idx] = mn[i] + e2;
            }
        }
    }
}

// ---------------------------------------------------------------------------
// Exact rescore (R12-proven core): scan tiles with lb <= min(ub); exact
// reference score fsub(fadd(rn,wn), 2*dot) with k-ascending FFMA chain;
// argmin, lowest-index ties.
__global__ __launch_bounds__(128)
void rescore_kernel(const float* __restrict__ emb, int h) {
    const int row = blockIdx.x, tid = threadIdx.x;
    __shared__ float rrow[DN];
    __shared__ float lbs[NTILES];
    __shared__ float ubs[NTILES];
    __shared__ float red[128];
    __shared__ float sv[128];
    __shared__ int   si[128];

    rrow[tid]      = g_resid[(size_t)row * DN + tid];
    lbs[tid]       = g_lb[(size_t)row * NTILES + tid];
    lbs[tid + 128] = g_lb[(size_t)row * NTILES + tid + 128];
    ubs[tid]       = g_ub[(size_t)row * NTILES + tid];
    ubs[tid + 128] = g_ub[(size_t)row * NTILES + tid + 128];
    __syncthreads();

    red[tid] = fminf(ubs[tid], ubs[tid + 128]);
    __syncthreads();
    #pragma unroll
    for (int o = 64; o; o >>= 1) {
        if (tid < o) red[tid] = fminf(red[tid], red[tid + o]);
        __syncthreads();
    }
    const float gminU = red[0];
    const float rn = g_rnorm[row];

    float bv = FLT_MAX; int bi = 0x7fffffff;
    const float* W  = emb + (size_t)h * KN * DN;
    const float* wn = g_wnorm + h * KN;

    for (int t = 0; t < NTILES; t++) {
        if (lbs[t] <= gminU) {
            const int c = t * NTILE + tid;       // ascending per thread over t
            const float* wr = W + (size_t)c * DN;
            float acc = 0.0f;
            #pragma unroll 8
            for (int k = 0; k < DN; k++)
                acc = __fmaf_rn(rrow[k], wr[k], acc);   // exact reference chain
            float s = __fsub_rn(__fadd_rn(rn, wn[c]), __fmul_rn(2.0f, acc));
            if (s < bv) { bv = s; bi = c; }             // strict: lowest idx per thread
        }
    }
    sv[tid] = bv; si[tid] = bi;
    __syncthreads();
    if (tid == 0) {
        float b = FLT_MAX; int bidx = 0x7fffffff;
        #pragma unroll 4
        for (int t2 = 0; t2 < 128; t2++) {
            float v = sv[t2]; int ii = si[t2];
            if (v < b || (v == b && ii < bidx)) { b = v; bidx = ii; }
        }
        g_codes[row * HN + h] = bidx;
    }
}

// ---------------------------------------------------------------------------
__global__ void update_kernel(const float* __restrict__ emb, int h) {
    int row = blockIdx.x;
    int c = g_codes[row * HN + h];
    float q = emb[(size_t)h * KN * DN + (size_t)c * DN + threadIdx.x];
    g_resid[(size_t)row * DN + threadIdx.x] = __fsub_rn(g_resid[(size_t)row * DN + threadIdx.x], q);
    g_quant[(size_t)row * DN + threadIdx.x] = __fadd_rn(g_quant[(size_t)row * DN + threadIdx.x], q);
}

__global__ void pack_kernel(float* __restrict__ out) {
    int i = blockIdx.x * blockDim.x + threadIdx.x;
    const int q0 = BN;
    const int c0 = BN + BN * DN;
    const int tot = c0 + BN * HN;
    if (i >= tot) return;
    if (i < q0)       out[i] = 0.0f;
    else if (i < c0)  out[i] = g_quant[i - q0];
    else              out[i] = (float)g_codes[i - c0];
}

// ---------------------------------------------------------------------------
extern "C" void kernel_launch(void* const* d_in, const int* in_sizes, int n_in,
                              void* d_out, int out_size) {
    const float* inputs = (const float*)d_in[0];   // (4096,1,128) fp32
    const float* emb    = (const float*)d_in[1];   // (3,32768,128) fp32
    float* out = (float*)d_out;

    prep_kernel<<<(BN * DN + 255) / 256, 256>>>(inputs);
    wnorm_kernel<<<(HN * KN) / 8, 256>>>(emb);
    embq_kernel<<<(HN * KN) / 8, 256>>>(emb);
    tilemax_kernel<<<(HN * NTILES + 7) / 8, 256>>>();

    for (int h = 0; h < HN; h++) {
        rnorm_kernel<<<BN / 8, 256>>>();             // exact XLA ||r||^2
        residq_kernel<<<BN / 8, 256>>>();            // int8 resid + scales
        screen_kernel<<<dim3(BN / 128, NSPLIT), TPB>>>(h);
        rescore_kernel<<<BN, 128>>>(emb, h);
        update_kernel<<<BN, 128>>>(emb, h);
    }

    const int tot = BN + BN * DN + BN * HN;
    pack_kernel<<<(tot + 255) / 256, 256>>>(out);
}

// round 16
// speedup vs baseline: 2.3751x; 2.3751x over previous
#include <cuda_runtime.h>
#include <float.h>

#define BN 4096
#define KN 32768
#define DN 128
#define HN 3
#define NSPLIT 32
#define MT 128
#define KT 256
#define DC 32
#define NT 256
#define AST4 130             // A smem stride per d-pair row (float4 units)
#define BSTRIDE 260          // B smem row stride (floats, even, mult of 4)

// smem layout (bytes)
#define SM_A    0                          // [64 d2][AST4] float4  = 133120 (+pad)
#define SM_B0   135232                     // [DC][BSTRIDE] float   = 33280
#define SM_B1   168512
#define SM_TOT  201792

// scratch (no allocations allowed)
__device__ float g_resid[BN * DN];
__device__ float g_quant[BN * DN];
__device__ float g_rnorm[BN];               // ||r||^2 per row (XLA-order fp32)
__device__ float g_wnorm[HN * KN];          // ||w||^2 per code row (XLA-order fp32)
__device__ float g_pbv[BN * NSPLIT];
__device__ int   g_pbi[BN * NSPLIT];
__device__ int   g_codes[BN * HN];

// Packed dual fp32 FMA. Each half is an independent IEEE fp32 FMA — bitwise
// identical to scalar __fmaf_rn, so k-ascending chain semantics are unchanged.
__device__ __forceinline__ void ffma2(unsigned long long& d,
                                      unsigned long long a,
                                      unsigned long long b) {
    asm("fma.rn.f32x2 %0, %1, %2, %3;" : "=l"(d) : "l"(a), "l"(b), "l"(d));
}

// ---------------------------------------------------------------------------
// XLA-style row reduction of sum(x*x): separate mul/add roundings + shfl tree.
__device__ __forceinline__ float row_sumsq_xla(const float* __restrict__ x, int lane) {
    float acc = 0.0f;
    #pragma unroll
    for (int i = 0; i < 4; i++) {
        float v = x[lane + 32 * i];
        acc = __fadd_rn(acc, __fmul_rn(v, v));
    }
    #pragma unroll
    for (int o = 16; o; o >>= 1)
        acc = __fadd_rn(acc, __shfl_down_sync(0xffffffffu, acc, o));
    return acc;
}

__global__ void wnorm_kernel(const float* __restrict__ emb) {
    int row  = blockIdx.x * 8 + (threadIdx.x >> 5);
    int lane = threadIdx.x & 31;
    if (row >= HN * KN) return;
    float s = row_sumsq_xla(emb + (size_t)row * DN, lane);
    if (lane == 0) g_wnorm[row] = s;
}

__global__ void rnorm_kernel() {
    int row  = blockIdx.x * 8 + (threadIdx.x >> 5);
    int lane = threadIdx.x & 31;
    if (row >= BN) return;
    float s = row_sumsq_xla(g_resid + (size_t)row * DN, lane);
    if (lane == 0) g_rnorm[row] = s;
}

__global__ void init_kernel(const float* __restrict__ in) {
    int i = blockIdx.x * blockDim.x + threadIdx.x;
    if (i < BN * DN) { g_resid[i] = in[i]; g_quant[i] = 0.0f; }
}

// ---------------------------------------------------------------------------
// B chunk loaders: register double-buffer. Each (it,thread) owns a code PAIR
// (2p, 2p+1) and a 4-d group -> 2 LDG.128 in, 4 STS.64 out (pair-packed).
__device__ __forceinline__ void ldgB(const float* __restrict__ W, int kBase, int dc,
                                     int tid, float4* pa, float4* pb) {
    #pragma unroll
    for (int it = 0; it < 4; it++) {
        int item = tid + NT * it;            // 0..1023
        int p  = item >> 3;                  // 0..127 code pair
        int d4 = item & 7;                   // 0..7
        const float* base = W + (size_t)(kBase + 2 * p) * DN + dc + d4 * 4;
        pa[it] = *(const float4*)base;         // code 2p
        pb[it] = *(const float4*)(base + DN);  // code 2p+1
    }
}
__device__ __forceinline__ void stsB(float* __restrict__ Bs, int tid,
                                     const float4* pa, const float4* pb) {
    #pragma unroll
    for (int it = 0; it < 4; it++) {
        int item = tid + NT * it;
        int p  = item >> 3;
        int d4 = item & 7;
        int c0 = 2 * p;
        // word(c) = ((c>>2)&3)*64 + (c>>4)*4 + (c&3); widx(c0+1) = widx(c0)+1
        int widx = ((c0 >> 2) & 3) * 64 + (c0 >> 4) * 4 + (c0 & 3);
        *(float2*)&Bs[(d4 * 4 + 0) * BSTRIDE + widx] = make_float2(pa[it].x, pb[it].x);
        *(float2*)&Bs[(d4 * 4 + 1) * BSTRIDE + widx] = make_float2(pa[it].y, pb[it].y);
        *(float2*)&Bs[(d4 * 4 + 2) * BSTRIDE + widx] = make_float2(pa[it].z, pb[it].z);
        *(float2*)&Bs[(d4 * 4 + 3) * BSTRIDE + widx] = make_float2(pa[it].w, pb[it].w);
    }
}

// ---------------------------------------------------------------------------
// 128-row x 256-code tile GEMM, packed FFMA2, 256 threads, 8x16 micro-tile.
// A preloaded once as float4 {v,v,w,w} per d-pair -> one LDS.128 feeds two d.
// B pair-packed, double-buffered in smem (ONE sync per 32-d chunk), global
// loads register-prefetched. Score replicates reference rounding exactly:
// s = fsub(fadd(rn,wn), 2*dot); argmin, strict < => lowest code index.
__global__ __launch_bounds__(NT, 1)
void argmax_kernel(const float* __restrict__ emb, int h) {
    extern __shared__ float smem[];
    float4* A4 = (float4*)smem;                    // [64][AST4] {v,v,w,w}
    float*  B0 = smem + SM_B0 / 4;
    float*  B1 = smem + SM_B1 / 4;

    const float* W  = emb + (size_t)h * KN * DN;
    const float* wn = g_wnorm + h * KN;

    const int mBase      = blockIdx.x * MT;
    const int kSplit     = KN / NSPLIT;            // 1024
    const int kSplitBase = blockIdx.y * kSplit;
    const int tid = threadIdx.x;
    const int tx = tid & 15, ty = tid >> 4;        // 16 x 16

    // ---- prefetch B chunk 0 into registers ----
    float4 pba[4], pbb[4];
    ldgB(W, kSplitBase, 0, tid, pba, pbb);

    // ---- preload A once: d-pair duplicated {v,v,w,w} ----
    #pragma unroll
    for (int it = 0; it < 32; it++) {
        int item = tid + NT * it;            // 0..8191
        int r  = item >> 6;                  // 0..127
        int d2 = item & 63;                  // 0..63
        float2 v = *(const float2*)&g_resid[(size_t)(mBase + r) * DN + d2 * 2];
        A4[d2 * AST4 + r] = make_float4(v.x, v.x, v.y, v.y);
    }

    // ---- stage chunk 0, prefetch chunk 1 ----
    stsB(B0, tid, pba, pbb);
    ldgB(W, kSplitBase, DC, tid, pba, pbb);
    __syncthreads();                         // A + B0 visible

    float bestv[8];
    int   besti[8];
    #pragma unroll
    for (int i = 0; i < 8; i++) { bestv[i] = FLT_MAX; besti[i] = 0; }

    float rn[8];
    #pragma unroll
    for (int i = 0; i < 8; i++) rn[i] = g_rnorm[mBase + i * 16 + ty];

    const int NKT = kSplit / KT;    // 4
    for (int kt = 0; kt < NKT; kt++) {
        const int kBase = kSplitBase + kt * KT;

        unsigned long long acc2[8][8];   // [row i][code pair p]
        #pragma unroll
        for (int i = 0; i < 8; i++)
            #pragma unroll
            for (int p = 0; p < 8; p++) acc2[i][p] = 0ull;

        for (int ch = 0; ch < 4; ch++) {
            const int ci = kt * 4 + ch;
            float* Bcur = (ci & 1) ? B1 : B0;

            // store next chunk into the other buffer; prefetch the one after
            if (ci + 1 < 16) {
                stsB((ci & 1) ? B0 : B1, tid, pba, pbb);
                if (ci + 2 < 16) {
                    int cj = ci + 2;
                    ldgB(W, kSplitBase + (cj >> 2) * KT, (cj & 3) * DC, tid, pba, pbb);
                }
            }

            #pragma unroll 4
            for (int dd2 = 0; dd2 < DC / 2; dd2++) {
                const int d2g = ch * (DC / 2) + dd2;       // d-pair WITHIN DN (0..63)
                const int dd  = dd2 * 2;                   // local d in chunk
                // A: one LDS.128 per row gives {a_d,a_d,a_d1,a_d1}
                ulonglong2 a4[8];
                #pragma unroll
                for (int i = 0; i < 8; i++)
                    a4[i] = *(const ulonglong2*)&A4[d2g * AST4 + i * 16 + ty];
                // d (even): k-ascending first
                {
                    ulonglong2 bq[4];
                    #pragma unroll
                    for (int q = 0; q < 4; q++)
                        bq[q] = *(const ulonglong2*)&Bcur[dd * BSTRIDE + q * 64 + tx * 4];
                    #pragma unroll
                    for (int i = 0; i < 8; i++)
                        #pragma unroll
                        for (int q = 0; q < 4; q++) {
                            ffma2(acc2[i][q * 2 + 0], a4[i].x, bq[q].x);
                            ffma2(acc2[i][q * 2 + 1], a4[i].x, bq[q].y);
                        }
                }
                // d+1: continues each accumulator's k-ascending chain
                {
                    ulonglong2 bq[4];
                    #pragma unroll
                    for (int q = 0; q < 4; q++)
                        bq[q] = *(const ulonglong2*)&Bcur[(dd + 1) * BSTRIDE + q * 64 + tx * 4];
                    #pragma unroll
                    for (int i = 0; i < 8; i++)
                        #pragma unroll
                        for (int q = 0; q < 4; q++) {
                            ffma2(acc2[i][q * 2 + 0], a4[i].y, bq[q].x);
                            ffma2(acc2[i][q * 2 + 1], a4[i].y, bq[q].y);
                        }
                }
            }
            __syncthreads();   // all reads of Bcur done; stsB(ci+1) complete
        }

        // epilogue: reference rounding events, ascending code order
        #pragma unroll
        for (int p = 0; p < 8; p++) {
            int    kk = kBase + tx * 16 + p * 2;
            float2 w2 = *(const float2*)&wn[kk];
            #pragma unroll
            for (int i = 0; i < 8; i++) {
                float dlo = __uint_as_float((unsigned)(acc2[i][p] & 0xffffffffull));
                float dhi = __uint_as_float((unsigned)(acc2[i][p] >> 32));
                float s  = __fsub_rn(__fadd_rn(rn[i], w2.x), __fmul_rn(2.0f, dlo));
                if (s < bestv[i]) { bestv[i] = s; besti[i] = kk; }
                float s2 = __fsub_rn(__fadd_rn(rn[i], w2.y), __fmul_rn(2.0f, dhi));
                if (s2 < bestv[i]) { bestv[i] = s2; besti[i] = kk + 1; }
            }
        }
    }

    // cross-thread reduction per row (tx lanes hold disjoint code sets)
    __syncthreads();
    float* sv = smem;                 // 2048 floats
    int*   si = (int*)(smem + 2048);  // 2048 ints
    #pragma unroll
    for (int i = 0; i < 8; i++) {
        int row = i * 16 + ty;
        sv[row * 16 + tx] = bestv[i];
        si[row * 16 + tx] = besti[i];
    }
    __syncthreads();
    if (tid < 128) {
        float bv = FLT_MAX; int bi = 0x7fffffff;
        #pragma unroll
        for (int t = 0; t < 16; t++) {
            float v = sv[tid * 16 + t]; int id = si[tid * 16 + t];
            if (v < bv || (v == bv && id < bi)) { bv = v; bi = id; }
        }
        g_pbv[(size_t)(mBase + tid) * NSPLIT + blockIdx.y] = bv;
        g_pbi[(size_t)(mBase + tid) * NSPLIT + blockIdx.y] = bi;
    }
}

// ---------------------------------------------------------------------------
__global__ void update_kernel(const float* __restrict__ emb, int h) {
    int row = blockIdx.x;     // BN blocks, 128 threads
    __shared__ int sc;
    if (threadIdx.x == 0) {
        float bv = FLT_MAX; int bi = 0x7fffffff;
        #pragma unroll
        for (int t = 0; t < NSPLIT; t++) {
            float v = g_pbv[(size_t)row * NSPLIT + t];
            int  id = g_pbi[(size_t)row * NSPLIT + t];
            if (v < bv || (v == bv && id < bi)) { bv = v; bi = id; }
        }
        g_codes[row * HN + h] = bi;
        sc = bi;
    }
    __syncthreads();
    int c = sc;
    float q = emb[(size_t)h * KN * DN + (size_t)c * DN + threadIdx.x];
    g_resid[(size_t)row * DN + threadIdx.x] = __fsub_rn(g_resid[(size_t)row * DN + threadIdx.x], q);
    g_quant[(size_t)row * DN + threadIdx.x] = __fadd_rn(g_quant[(size_t)row * DN + threadIdx.x], q);
}

// ---------------------------------------------------------------------------
__global__ void pack_kernel(float* __restrict__ out) {
    int i = blockIdx.x * blockDim.x + threadIdx.x;
    const int q0 = BN;
    const int c0 = BN + BN * DN;
    const int tot = c0 + BN * HN;
    if (i >= tot) return;
    if (i < q0)       out[i] = 0.0f;
    else if (i < c0)  out[i] = g_quant[i - q0];
    else              out[i] = (float)g_codes[i - c0];
}

// ---------------------------------------------------------------------------
extern "C" void kernel_launch(void* const* d_in, const int* in_sizes, int n_in,
                              void* d_out, int out_size) {
    const float* inputs = (const float*)d_in[0];   // (4096,1,128) fp32
    const float* emb    = (const float*)d_in[1];   // (3,32768,128) fp32
    float* out = (float*)d_out;

    cudaFuncSetAttribute(argmax_kernel, cudaFuncAttributeMaxDynamicSharedMemorySize, SM_TOT);

    wnorm_kernel<<<(HN * KN) / 8, 256>>>(emb);
    init_kernel<<<(BN * DN + 255) / 256, 256>>>(inputs);

    for (int h = 0; h < HN; h++) {
        rnorm_kernel<<<BN / 8, 256>>>();           // XLA-order ||r||^2 of current resid
        dim3 grid(BN / MT, NSPLIT);
        argmax_kernel<<<grid, NT, SM_TOT>>>(emb, h);
        update_kernel<<<BN, 128>>>(emb, h);
    }

    const int tot = BN + BN * DN + BN * HN;
    pack_kernel<<<(tot + 255) / 256, 256>>>(out);
}